// round 14
// baseline (speedup 1.0000x reference)
#include <cuda_runtime.h>
#include <cuda_fp16.h>
#include <cstdint>

#define Bz 4
#define Sq 4096
#define Dd 1024
#define MS (Bz * Sq)

typedef __half fp16;

// ---------------- scratch (device globals; no allocations allowed) --------
__device__ fp16 g_Xh[(size_t)MS * Dd];
__device__ fp16 g_Wh[3][Dd * Dd];
__device__ fp16 g_Qh[(size_t)MS * Dd];
__device__ fp16 g_Kh[(size_t)MS * Dd];
__device__ fp16 g_Vh[(size_t)MS * Dd];
__device__ fp16 g_Vth[(size_t)MS * Dd];          // V^T: [b][d][s]
__device__ fp16 g_E[(size_t)Bz * Sq * Sq];       // exp(scores), unnormalized
__device__ float g_RSp[(size_t)Bz * 32 * Sq];    // per-tile row partial sums

// =========================== PTX helpers ==================================
__device__ __forceinline__ uint32_t smem_u32(const void* p) {
    uint32_t a;
    asm("{ .reg .u64 t; cvta.to.shared.u64 t, %1; cvt.u32.u64 %0, t; }"
        : "=r"(a) : "l"(p));
    return a;
}
__device__ __forceinline__ void cp16(uint32_t s, const void* g) {
    asm volatile("cp.async.cg.shared.global [%0], [%1], 16;" :: "r"(s), "l"(g));
}
__device__ __forceinline__ void cp_commit() {
    asm volatile("cp.async.commit_group;" ::: "memory");
}
__device__ __forceinline__ void cp_wait1() {
    asm volatile("cp.async.wait_group 1;" ::: "memory");
}
__device__ __forceinline__ void ldm_x4(uint32_t a, uint32_t& r0, uint32_t& r1,
                                       uint32_t& r2, uint32_t& r3) {
    asm volatile("ldmatrix.sync.aligned.m8n8.x4.shared.b16 {%0,%1,%2,%3}, [%4];"
                 : "=r"(r0), "=r"(r1), "=r"(r2), "=r"(r3) : "r"(a));
}
__device__ __forceinline__ void mma_f16(float (&c)[4],
                                        const uint32_t (&a)[4],
                                        uint32_t b0, uint32_t b1) {
    asm volatile("mma.sync.aligned.m16n8k16.row.col.f32.f16.f16.f32 "
                 "{%0,%1,%2,%3}, {%4,%5,%6,%7}, {%8,%9}, {%0,%1,%2,%3};"
                 : "+f"(c[0]), "+f"(c[1]), "+f"(c[2]), "+f"(c[3])
                 : "r"(a[0]), "r"(a[1]), "r"(a[2]), "r"(a[3]), "r"(b0), "r"(b1));
}

// =========================== GEMM core ====================================
// C[128,128] = A[128,kLen] * B[128,kLen]^T, K-major fp16, KC=64, 3-stage
// cp.async, 128 threads, warp grid 2(M) x 2(N), warp tile 64x64, 2 CTA/SM.
// A-fragments software-pipelined (double-buffered) across tm groups;
// prefetch LDGSTS issued in the MMA shadow after k16=0.
// MODE 0: fp16 out                                   (QKV)
// MODE 2: fp16 out = exp(acc*scale), diag-masked; writes per-tile row sums
// MODE 3: fp32 out = acc * s_inv[row]; s_inv built from partials in prologue
#define KC 64
#define PLANE_B 16384
#define STAGE   (2 * PLANE_B)
#define SMEM_G  (3 * STAGE + 2048)   // pipeline + reduction scratch
#define NT 128

__device__ __forceinline__ void stage_copy(uint32_t sb, int tid,
    const fp16* __restrict__ Ah, int lda,
    const fp16* __restrict__ Bh, int ldb, int k0)
{
#pragma unroll
    for (int i = 0; i < 8; i++) {
        int q = tid + (i << 7);
        int m = q >> 3, c = q & 7;
        uint32_t so = (uint32_t)(m * 128 + ((c ^ (m & 7)) << 4));
        cp16(sb + so,           Ah + (size_t)m * lda + k0 + c * 8);
        cp16(sb + PLANE_B + so, Bh + (size_t)m * ldb + k0 + c * 8);
    }
}

template <int MODE>
__device__ __forceinline__ void gemm_core(
    const fp16* __restrict__ Ah, int lda,
    const fp16* __restrict__ Bh, int ldb,
    int kLen,
    float* __restrict__ Cf, fp16* __restrict__ Ch,
    int ldc, float scale, int diag,
    float* __restrict__ rsp)      // MODE2: write base; MODE3: read base
{
    extern __shared__ char dyn[];
    const uint32_t sbase = smem_u32(dyn);
    float* sred = (float*)(dyn + 3 * STAGE);   // 2KB scratch
    const int tid = threadIdx.x;
    const int l = tid & 31, wid = tid >> 5;
    const int wm = wid & 1, wn = wid >> 1;     // 2 x 2 warp grid
    const int kT = kLen >> 6;

    float acc[4][8][4];
#pragma unroll
    for (int i = 0; i < 4; i++)
#pragma unroll
        for (int j = 0; j < 8; j++)
#pragma unroll
            for (int k = 0; k < 4; k++) acc[i][j][k] = 0.f;

    stage_copy(sbase, tid, Ah, lda, Bh, ldb, 0);
    cp_commit();
    if (kT > 1) stage_copy(sbase + STAGE, tid, Ah, lda, Bh, ldb, KC);
    cp_commit();

    // PV prologue: build inverse row sums from per-tile partials
    if (MODE == 3) {
        const int nkt = kLen >> 7;
        float s = 0.f;
        for (int kt = 0; kt < nkt; kt++)
            s += rsp[(size_t)kt * Sq + tid];
        sred[tid] = 1.0f / s;
    }

    const int arow = l & 15;
    const int c0A  = (l >> 4) & 1;
    const int brow = (l & 7) + ((l & 16) >> 1);
    const int c0B  = (l >> 3) & 1;
    const int lm7  = l & 7;
    const int aRowBase = wm * 64 + arow;
    const int bRowBase = wn * 64 + brow;

    int slot = 0;
    for (int kt = 0; kt < kT; kt++) {
        cp_wait1();
        __syncthreads();

        const uint32_t sb = sbase + slot * STAGE;
        const int ps = (slot + 2 >= 3) ? slot - 1 : slot + 2;
        if (++slot == 3) slot = 0;

#pragma unroll
        for (int k16 = 0; k16 < 4; k16++) {
            const uint32_t kcolB = (uint32_t)(((2 * k16 + c0B) ^ lm7) << 4);
            const uint32_t kcolA = (uint32_t)(((2 * k16 + c0A) ^ lm7) << 4);

            uint32_t bh[8][2];
#pragma unroll
            for (int pr = 0; pr < 4; pr++) {
                uint32_t off = (uint32_t)((bRowBase + pr * 16) * 128) + kcolB;
                uint32_t r0, r1, r2, r3;
                ldm_x4(sb + PLANE_B + off, r0, r1, r2, r3);
                bh[pr * 2][0] = r0; bh[pr * 2][1] = r1;
                bh[pr * 2 + 1][0] = r2; bh[pr * 2 + 1][1] = r3;
            }

            // A double-buffer: load A(0) up front, A(tm+1) before tm's MMAs
            uint32_t ah[2][4];
            ldm_x4(sb + (uint32_t)(aRowBase * 128) + kcolA,
                   ah[0][0], ah[0][1], ah[0][2], ah[0][3]);
#pragma unroll
            for (int tm = 0; tm < 4; tm++) {
                if (tm < 3) {
                    uint32_t off = (uint32_t)((aRowBase + (tm + 1) * 16) * 128)
                                 + kcolA;
                    uint32_t (&nx)[4] = ah[(tm + 1) & 1];
                    ldm_x4(sb + off, nx[0], nx[1], nx[2], nx[3]);
                }
                const uint32_t (&cur)[4] = ah[tm & 1];
#pragma unroll
                for (int tn = 0; tn < 8; tn++)
                    mma_f16(acc[tm][tn], cur, bh[tn][0], bh[tn][1]);
            }
            // next-stage LDGSTS in the MMA shadow, after k16=0 is rolling
            if (k16 == 0) {
                if (kt + 2 < kT)
                    stage_copy(sbase + ps * STAGE, tid, Ah, lda, Bh, ldb,
                               (kt + 2) * KC);
                cp_commit();   // exactly one commit per kt (group may be empty)
            }
        }
    }

    // epilogue
    const int g = l >> 2, tg = l & 3;
#pragma unroll
    for (int tm = 0; tm < 4; tm++) {
        const int r0 = wm * 64 + tm * 16 + g;
        float p0 = 0.f, p1 = 0.f;   // MODE2 row partial sums (rows r0, r0+8)
#pragma unroll
        for (int tn = 0; tn < 8; tn++) {
            const int col = wn * 64 + tn * 8 + tg * 2;
            const float* a = acc[tm][tn];
            if (MODE == 3) {
                const float i0 = sred[r0], i1 = sred[r0 + 8];
                *(float2*)(Cf + (size_t)r0 * ldc + col) =
                    make_float2(a[0] * i0, a[1] * i0);
                *(float2*)(Cf + (size_t)(r0 + 8) * ldc + col) =
                    make_float2(a[2] * i1, a[3] * i1);
            } else if (MODE == 2) {
                float e0 = __expf(a[0] * scale);
                float e1 = __expf(a[1] * scale);
                float e2 = __expf(a[2] * scale);
                float e3 = __expf(a[3] * scale);
                if (diag) {
                    if (col     > r0)     e0 = 0.f;
                    if (col + 1 > r0)     e1 = 0.f;
                    if (col     > r0 + 8) e2 = 0.f;
                    if (col + 1 > r0 + 8) e3 = 0.f;
                }
                p0 += e0 + e1;
                p1 += e2 + e3;
                *(__half2*)(Ch + (size_t)r0 * ldc + col) =
                    __halves2half2(__float2half_rn(e0), __float2half_rn(e1));
                *(__half2*)(Ch + (size_t)(r0 + 8) * ldc + col) =
                    __halves2half2(__float2half_rn(e2), __float2half_rn(e3));
            } else {
#pragma unroll
                for (int h = 0; h < 2; h++) {
                    size_t o = (size_t)(r0 + 8 * h) * ldc + col;
                    *(__half2*)(Ch + o) = __halves2half2(
                        __float2half_rn(a[2 * h]), __float2half_rn(a[2 * h + 1]));
                }
            }
        }
        if (MODE == 2) {
            p0 += __shfl_xor_sync(0xffffffffu, p0, 1);
            p0 += __shfl_xor_sync(0xffffffffu, p0, 2);
            p1 += __shfl_xor_sync(0xffffffffu, p1, 1);
            p1 += __shfl_xor_sync(0xffffffffu, p1, 2);
            if (tg == 0) {
                sred[r0 * 2 + wn]       = p0;
                sred[(r0 + 8) * 2 + wn] = p1;
            }
        }
    }
    if (MODE == 2) {
        __syncthreads();
        float s = sred[tid * 2] + sred[tid * 2 + 1];
        rsp[tid] = s;
    }
}

// =========================== GEMM kernels =================================
__global__ __launch_bounds__(NT, 2)
void k_qkv()
{
    const int z = blockIdx.z;
    fp16* Oh = (z == 0) ? g_Qh : (z == 1) ? g_Kh : g_Vh;
    const size_t m0 = (size_t)blockIdx.y * 128;
    const size_t n0 = (size_t)blockIdx.x * 128;
    gemm_core<0>(g_Xh + m0 * Dd, Dd, g_Wh[z] + n0 * Dd, Dd, Dd,
                 nullptr, Oh + m0 * Dd + n0, Dd, 1.0f, 0, nullptr);
}

__global__ __launch_bounds__(NT, 2)
void k_scores()
{
    // triangular decode: t -> (qt, kt), kt <= qt
    const int t = blockIdx.x, b = blockIdx.y;
    int qt = (int)((sqrtf(8.f * (float)t + 1.f) - 1.f) * 0.5f);
    while ((qt + 1) * (qt + 2) / 2 <= t) qt++;
    while (qt * (qt + 1) / 2 > t) qt--;
    const int kt = t - qt * (qt + 1) / 2;

    const size_t qo = (size_t)b * Sq * Dd + (size_t)qt * 128 * Dd;
    const size_t ko = (size_t)b * Sq * Dd + (size_t)kt * 128 * Dd;
    gemm_core<2>(g_Qh + qo, Dd, g_Kh + ko, Dd, Dd,
                 nullptr,
                 g_E + (size_t)b * Sq * Sq + (size_t)qt * 128 * Sq + kt * 128,
                 Sq, 0.03125f, kt == qt,
                 g_RSp + ((size_t)b * 32 + kt) * Sq + (size_t)qt * 128);
}

__global__ __launch_bounds__(NT, 2)
void k_pv(float* __restrict__ out)
{
    const int b = blockIdx.z;
    const size_t m0 = (size_t)blockIdx.y * 128;
    const size_t n0 = (size_t)blockIdx.x * 128;
    const size_t po = (size_t)b * Sq * Sq + m0 * Sq;
    const size_t vo = (size_t)b * Sq * Dd + n0 * Sq;
    gemm_core<3>(g_E + po, Sq, g_Vth + vo, Sq, (int)(m0 + 128),
                 out + (size_t)b * Sq * Dd + m0 * Dd + n0,
                 nullptr, Dd, 1.0f, 0,
                 g_RSp + (size_t)b * 32 * Sq + m0);
}

// =========================== aux kernels ==================================
__global__ __launch_bounds__(256)
void k_cvtX(const float* __restrict__ s, fp16* __restrict__ h)
{
    int i = blockIdx.x * 256 + threadIdx.x;
    float4 v = ((const float4*)s)[i];
    ((__half2*)h)[2 * i]     = __halves2half2(__float2half_rn(v.x), __float2half_rn(v.y));
    ((__half2*)h)[2 * i + 1] = __halves2half2(__float2half_rn(v.z), __float2half_rn(v.w));
}

__global__ __launch_bounds__(256)
void k_cvtW(const float* __restrict__ wq, const float* __restrict__ wk,
            const float* __restrict__ wv)
{
    const int z = blockIdx.y;
    const float* s = (z == 0) ? wq : (z == 1) ? wk : wv;
    fp16* h = g_Wh[z];
    int i = blockIdx.x * 256 + threadIdx.x;
    float4 v = ((const float4*)s)[i];
    ((__half2*)h)[2 * i]     = __halves2half2(__float2half_rn(v.x), __float2half_rn(v.y));
    ((__half2*)h)[2 * i + 1] = __halves2half2(__float2half_rn(v.z), __float2half_rn(v.w));
}

__global__ void k_vtrans()
{
    __shared__ fp16 t[32][33];
    const int b = blockIdx.z;
    const fp16* V = g_Vh  + (size_t)b * Sq * Dd;
    fp16*       T = g_Vth + (size_t)b * Sq * Dd;
    const int s0 = blockIdx.x * 32, d0 = blockIdx.y * 32;
    const int x = threadIdx.x, y = threadIdx.y;
#pragma unroll
    for (int i = 0; i < 32; i += 8)
        t[y + i][x] = V[(size_t)(s0 + y + i) * Dd + d0 + x];
    __syncthreads();
#pragma unroll
    for (int i = 0; i < 32; i += 8)
        T[(size_t)(d0 + y + i) * Sq + s0 + x] = t[x][y + i];
}

// ===========================================================================
extern "C" void kernel_launch(void* const* d_in, const int* in_sizes, int n_in,
                              void* d_out, int out_size)
{
    const float* X  = (const float*)d_in[0];
    const float* Wq = (const float*)d_in[1];
    const float* Wk = (const float*)d_in[2];
    const float* Wv = (const float*)d_in[3];
    float* out = (float*)d_out;

    cudaFuncSetAttribute(k_qkv,    cudaFuncAttributeMaxDynamicSharedMemorySize, SMEM_G);
    cudaFuncSetAttribute(k_scores, cudaFuncAttributeMaxDynamicSharedMemorySize, SMEM_G);
    cudaFuncSetAttribute(k_pv,     cudaFuncAttributeMaxDynamicSharedMemorySize, SMEM_G);

    fp16* xh;
    cudaGetSymbolAddress((void**)&xh, g_Xh);

    k_cvtX<<<MS * Dd / 4 / 256, 256>>>(X, xh);                       // idx 0
    k_cvtW<<<dim3(Dd * Dd / 4 / 256, 3), 256>>>(Wq, Wk, Wv);         // idx 1
    k_qkv<<<dim3(Dd / 128, MS / 128, 3), NT, SMEM_G>>>();            // idx 2
    k_scores<<<dim3(528, Bz), NT, SMEM_G>>>();                       // idx 3 (ncu)
    k_vtrans<<<dim3(Sq / 32, Dd / 32, Bz), dim3(32, 8)>>>();         // idx 4
    k_pv<<<dim3(Dd / 128, Sq / 128, Bz), NT, SMEM_G>>>(out);         // idx 5
}

// round 16
// speedup vs baseline: 1.0261x; 1.0261x over previous
#include <cuda_runtime.h>
#include <cuda_fp16.h>
#include <cstdint>

#define Bz 4
#define Sq 4096
#define Dd 1024
#define MS (Bz * Sq)

typedef __half fp16;

// ---------------- scratch (device globals; no allocations allowed) --------
__device__ fp16 g_Xh[(size_t)MS * Dd];
__device__ fp16 g_Wh[3][Dd * Dd];
__device__ fp16 g_Qh[(size_t)MS * Dd];
__device__ fp16 g_Kh[(size_t)MS * Dd];
__device__ fp16 g_Vth[(size_t)MS * Dd];          // V^T: [b][d][s] (written directly)
__device__ fp16 g_E[(size_t)Bz * Sq * Sq];       // exp(scores), unnormalized
__device__ float g_RSp[(size_t)Bz * 32 * Sq];    // per-tile row partial sums

// =========================== PTX helpers ==================================
__device__ __forceinline__ uint32_t smem_u32(const void* p) {
    uint32_t a;
    asm("{ .reg .u64 t; cvta.to.shared.u64 t, %1; cvt.u32.u64 %0, t; }"
        : "=r"(a) : "l"(p));
    return a;
}
__device__ __forceinline__ void cp16(uint32_t s, const void* g) {
    asm volatile("cp.async.cg.shared.global [%0], [%1], 16;" :: "r"(s), "l"(g));
}
__device__ __forceinline__ void cp_commit() {
    asm volatile("cp.async.commit_group;" ::: "memory");
}
__device__ __forceinline__ void cp_wait1() {
    asm volatile("cp.async.wait_group 1;" ::: "memory");
}
__device__ __forceinline__ void ldm_x4(uint32_t a, uint32_t& r0, uint32_t& r1,
                                       uint32_t& r2, uint32_t& r3) {
    asm volatile("ldmatrix.sync.aligned.m8n8.x4.shared.b16 {%0,%1,%2,%3}, [%4];"
                 : "=r"(r0), "=r"(r1), "=r"(r2), "=r"(r3) : "r"(a));
}
__device__ __forceinline__ void mma_f16(float (&c)[4],
                                        const uint32_t (&a)[4],
                                        uint32_t b0, uint32_t b1) {
    asm volatile("mma.sync.aligned.m16n8k16.row.col.f32.f16.f16.f32 "
                 "{%0,%1,%2,%3}, {%4,%5,%6,%7}, {%8,%9}, {%0,%1,%2,%3};"
                 : "+f"(c[0]), "+f"(c[1]), "+f"(c[2]), "+f"(c[3])
                 : "r"(a[0]), "r"(a[1]), "r"(a[2]), "r"(a[3]), "r"(b0), "r"(b1));
}

// =========================== GEMM core ====================================
// C[128,128] = A[128,kLen] * B[128,kLen]^T, K-major fp16, KC=64, 3-stage
// cp.async, 128 threads, warp grid 2(M) x 2(N), warp tile 64x64, 2 CTA/SM.
// Prefetch LDGSTS issued in the MMA shadow after k16=0 (R13 mainloop).
// MODE 0: fp16 out                                   (Q, K)
// MODE 1: fp16 out TRANSPOSED via smem               (V -> g_Vt directly)
// MODE 2: fp16 out = exp(acc*scale), diag-masked; writes per-tile row sums
// MODE 3: fp32 out = acc * s_inv[row]; s_inv built from partials in prologue
#define KC 64
#define PLANE_B 16384
#define STAGE   (2 * PLANE_B)
#define SMEM_G  (3 * STAGE + 2048)   // pipeline + reduction scratch
#define NT 128

__device__ __forceinline__ void stage_copy(uint32_t sb, int tid,
    const fp16* __restrict__ Ah, int lda,
    const fp16* __restrict__ Bh, int ldb, int k0)
{
#pragma unroll
    for (int i = 0; i < 8; i++) {
        int q = tid + (i << 7);
        int m = q >> 3, c = q & 7;
        uint32_t so = (uint32_t)(m * 128 + ((c ^ (m & 7)) << 4));
        cp16(sb + so,           Ah + (size_t)m * lda + k0 + c * 8);
        cp16(sb + PLANE_B + so, Bh + (size_t)m * ldb + k0 + c * 8);
    }
}

template <int MODE>
__device__ __forceinline__ void gemm_core(
    const fp16* __restrict__ Ah, int lda,
    const fp16* __restrict__ Bh, int ldb,
    int kLen,
    float* __restrict__ Cf, fp16* __restrict__ Ch,
    int ldc, float scale, int diag,
    float* __restrict__ rsp)      // MODE2: write base; MODE3: read base
{
    extern __shared__ char dyn[];
    const uint32_t sbase = smem_u32(dyn);
    float* sred = (float*)(dyn + 3 * STAGE);   // 2KB scratch
    const int tid = threadIdx.x;
    const int l = tid & 31, wid = tid >> 5;
    const int wm = wid & 1, wn = wid >> 1;     // 2 x 2 warp grid
    const int kT = kLen >> 6;

    float acc[4][8][4];
#pragma unroll
    for (int i = 0; i < 4; i++)
#pragma unroll
        for (int j = 0; j < 8; j++)
#pragma unroll
            for (int k = 0; k < 4; k++) acc[i][j][k] = 0.f;

    stage_copy(sbase, tid, Ah, lda, Bh, ldb, 0);
    cp_commit();
    if (kT > 1) stage_copy(sbase + STAGE, tid, Ah, lda, Bh, ldb, KC);
    cp_commit();

    // PV prologue: build inverse row sums from per-tile partials
    if (MODE == 3) {
        const int nkt = kLen >> 7;
        float s = 0.f;
        for (int kt = 0; kt < nkt; kt++)
            s += rsp[(size_t)kt * Sq + tid];
        sred[tid] = 1.0f / s;
    }

    const int arow = l & 15;
    const int c0A  = (l >> 4) & 1;
    const int brow = (l & 7) + ((l & 16) >> 1);
    const int c0B  = (l >> 3) & 1;
    const int lm7  = l & 7;
    const int aRowBase = wm * 64 + arow;
    const int bRowBase = wn * 64 + brow;

    int slot = 0;
    for (int kt = 0; kt < kT; kt++) {
        cp_wait1();
        __syncthreads();

        const uint32_t sb = sbase + slot * STAGE;
        const int ps = (slot + 2 >= 3) ? slot - 1 : slot + 2;
        if (++slot == 3) slot = 0;

#pragma unroll
        for (int k16 = 0; k16 < 4; k16++) {
            uint32_t bh[8][2];
#pragma unroll
            for (int pr = 0; pr < 4; pr++) {
                uint32_t off = (uint32_t)((bRowBase + pr * 16) * 128)
                             + (uint32_t)(((2 * k16 + c0B) ^ lm7) << 4);
                uint32_t r0, r1, r2, r3;
                ldm_x4(sb + PLANE_B + off, r0, r1, r2, r3);
                bh[pr * 2][0] = r0; bh[pr * 2][1] = r1;
                bh[pr * 2 + 1][0] = r2; bh[pr * 2 + 1][1] = r3;
            }
#pragma unroll
            for (int tm = 0; tm < 4; tm++) {
                uint32_t off = (uint32_t)((aRowBase + tm * 16) * 128)
                             + (uint32_t)(((2 * k16 + c0A) ^ lm7) << 4);
                uint32_t ah[4];
                ldm_x4(sb + off, ah[0], ah[1], ah[2], ah[3]);
#pragma unroll
                for (int tn = 0; tn < 8; tn++)
                    mma_f16(acc[tm][tn], ah, bh[tn][0], bh[tn][1]);
            }
            // next-stage LDGSTS in the MMA shadow, after k16=0 is rolling
            if (k16 == 0) {
                if (kt + 2 < kT)
                    stage_copy(sbase + ps * STAGE, tid, Ah, lda, Bh, ldb,
                               (kt + 2) * KC);
                cp_commit();   // exactly one commit per kt (group may be empty)
            }
        }
    }

    // ---------------- epilogues ----------------
    const int g = l >> 2, tg = l & 3;

    if (MODE == 1) {
        // V: stage tile in smem (swizzled half2 [128][64]), write transposed.
        __syncthreads();                       // mainloop smem reads done
        __half2* tsm = (__half2*)dyn;
#pragma unroll
        for (int tm = 0; tm < 4; tm++) {
            const int r0 = wm * 64 + tm * 16 + g;
#pragma unroll
            for (int tn = 0; tn < 8; tn++) {
                const int c2 = wn * 32 + tn * 4 + tg;
                const float* a = acc[tm][tn];
                tsm[r0 * 64 + (c2 ^ (r0 & 31))] =
                    __halves2half2(__float2half_rn(a[0]), __float2half_rn(a[1]));
                tsm[(r0 + 8) * 64 + (c2 ^ ((r0 + 8) & 31))] =
                    __halves2half2(__float2half_rn(a[2]), __float2half_rn(a[3]));
            }
        }
        __syncthreads();
        // thread t writes d-row (tile col t): 128 fp16 contiguous in Vt
        const int c2r = tid >> 1, hsel = tid & 1;
        fp16* dst = Ch + (size_t)tid * ldc;    // Ch = Vt tile base, ldc = Sq
#pragma unroll
        for (int s8 = 0; s8 < 128; s8 += 8) {
            fp16 tmp[8];
#pragma unroll
            for (int j = 0; j < 8; j++) {
                __half2 w = tsm[(s8 + j) * 64 + (c2r ^ ((s8 + j) & 31))];
                tmp[j] = hsel ? __high2half(w) : __low2half(w);
            }
            *(uint4*)(dst + s8) = *(uint4*)tmp;
        }
        return;
    }

#pragma unroll
    for (int tm = 0; tm < 4; tm++) {
        const int r0 = wm * 64 + tm * 16 + g;
        float p0 = 0.f, p1 = 0.f;   // MODE2 row partial sums (rows r0, r0+8)
#pragma unroll
        for (int tn = 0; tn < 8; tn++) {
            const int col = wn * 64 + tn * 8 + tg * 2;
            const float* a = acc[tm][tn];
            if (MODE == 3) {
                const float i0 = sred[r0], i1 = sred[r0 + 8];
                *(float2*)(Cf + (size_t)r0 * ldc + col) =
                    make_float2(a[0] * i0, a[1] * i0);
                *(float2*)(Cf + (size_t)(r0 + 8) * ldc + col) =
                    make_float2(a[2] * i1, a[3] * i1);
            } else if (MODE == 2) {
                float e0 = __expf(a[0] * scale);
                float e1 = __expf(a[1] * scale);
                float e2 = __expf(a[2] * scale);
                float e3 = __expf(a[3] * scale);
                if (diag) {
                    if (col     > r0)     e0 = 0.f;
                    if (col + 1 > r0)     e1 = 0.f;
                    if (col     > r0 + 8) e2 = 0.f;
                    if (col + 1 > r0 + 8) e3 = 0.f;
                }
                p0 += e0 + e1;
                p1 += e2 + e3;
                *(__half2*)(Ch + (size_t)r0 * ldc + col) =
                    __halves2half2(__float2half_rn(e0), __float2half_rn(e1));
                *(__half2*)(Ch + (size_t)(r0 + 8) * ldc + col) =
                    __halves2half2(__float2half_rn(e2), __float2half_rn(e3));
            } else {
#pragma unroll
                for (int h = 0; h < 2; h++) {
                    size_t o = (size_t)(r0 + 8 * h) * ldc + col;
                    *(__half2*)(Ch + o) = __halves2half2(
                        __float2half_rn(a[2 * h]), __float2half_rn(a[2 * h + 1]));
                }
            }
        }
        if (MODE == 2) {
            p0 += __shfl_xor_sync(0xffffffffu, p0, 1);
            p0 += __shfl_xor_sync(0xffffffffu, p0, 2);
            p1 += __shfl_xor_sync(0xffffffffu, p1, 1);
            p1 += __shfl_xor_sync(0xffffffffu, p1, 2);
            if (tg == 0) {
                sred[r0 * 2 + wn]       = p0;
                sred[(r0 + 8) * 2 + wn] = p1;
            }
        }
    }
    if (MODE == 2) {
        __syncthreads();
        float s = sred[tid * 2] + sred[tid * 2 + 1];
        rsp[tid] = s;
    }
}

// =========================== GEMM kernels =================================
__global__ __launch_bounds__(NT, 2)
void k_qkv()
{
    const int z = blockIdx.z;
    const size_t m0 = (size_t)blockIdx.y * 128;   // global token row (b*Sq + s0)
    const size_t n0 = (size_t)blockIdx.x * 128;   // output feature col
    if (z == 2) {
        // V: write transposed directly into g_Vt, batch-blocked [b][d][s]
        const size_t b  = blockIdx.y >> 5;        // 32 = Sq/128 tiles per batch
        const size_t s0 = (size_t)(blockIdx.y & 31) * 128;
        gemm_core<1>(g_Xh + m0 * Dd, Dd, g_Wh[2] + n0 * Dd, Dd, Dd,
                     nullptr,
                     g_Vth + b * (size_t)Sq * Dd + n0 * Sq + s0,
                     Sq, 1.0f, 0, nullptr);
    } else {
        fp16* Oh = (z == 0) ? g_Qh : g_Kh;
        gemm_core<0>(g_Xh + m0 * Dd, Dd, g_Wh[z] + n0 * Dd, Dd, Dd,
                     nullptr, Oh + m0 * Dd + n0, Dd, 1.0f, 0, nullptr);
    }
}

__global__ __launch_bounds__(NT, 2)
void k_scores()
{
    // triangular decode: t -> (qt, kt), kt <= qt
    const int t = blockIdx.x, b = blockIdx.y;
    int qt = (int)((sqrtf(8.f * (float)t + 1.f) - 1.f) * 0.5f);
    while ((qt + 1) * (qt + 2) / 2 <= t) qt++;
    while (qt * (qt + 1) / 2 > t) qt--;
    const int kt = t - qt * (qt + 1) / 2;

    const size_t qo = (size_t)b * Sq * Dd + (size_t)qt * 128 * Dd;
    const size_t ko = (size_t)b * Sq * Dd + (size_t)kt * 128 * Dd;
    gemm_core<2>(g_Qh + qo, Dd, g_Kh + ko, Dd, Dd,
                 nullptr,
                 g_E + (size_t)b * Sq * Sq + (size_t)qt * 128 * Sq + kt * 128,
                 Sq, 0.03125f, kt == qt,
                 g_RSp + ((size_t)b * 32 + kt) * Sq + (size_t)qt * 128);
}

__global__ __launch_bounds__(NT, 2)
void k_pv(float* __restrict__ out)
{
    const int b = blockIdx.z;
    const size_t m0 = (size_t)blockIdx.y * 128;
    const size_t n0 = (size_t)blockIdx.x * 128;
    const size_t po = (size_t)b * Sq * Sq + m0 * Sq;
    const size_t vo = (size_t)b * Sq * Dd + n0 * Sq;
    gemm_core<3>(g_E + po, Sq, g_Vth + vo, Sq, (int)(m0 + 128),
                 out + (size_t)b * Sq * Dd + m0 * Dd + n0,
                 nullptr, Dd, 1.0f, 0,
                 g_RSp + (size_t)b * 32 * Sq + m0);
}

// =========================== aux kernels ==================================
__global__ __launch_bounds__(256)
void k_cvtX(const float* __restrict__ s, fp16* __restrict__ h)
{
    int i = blockIdx.x * 256 + threadIdx.x;
    float4 v = ((const float4*)s)[i];
    ((__half2*)h)[2 * i]     = __halves2half2(__float2half_rn(v.x), __float2half_rn(v.y));
    ((__half2*)h)[2 * i + 1] = __halves2half2(__float2half_rn(v.z), __float2half_rn(v.w));
}

__global__ __launch_bounds__(256)
void k_cvtW(const float* __restrict__ wq, const float* __restrict__ wk,
            const float* __restrict__ wv)
{
    const int z = blockIdx.y;
    const float* s = (z == 0) ? wq : (z == 1) ? wk : wv;
    fp16* h = g_Wh[z];
    int i = blockIdx.x * 256 + threadIdx.x;
    float4 v = ((const float4*)s)[i];
    ((__half2*)h)[2 * i]     = __halves2half2(__float2half_rn(v.x), __float2half_rn(v.y));
    ((__half2*)h)[2 * i + 1] = __halves2half2(__float2half_rn(v.z), __float2half_rn(v.w));
}

// ===========================================================================
extern "C" void kernel_launch(void* const* d_in, const int* in_sizes, int n_in,
                              void* d_out, int out_size)
{
    const float* X  = (const float*)d_in[0];
    const float* Wq = (const float*)d_in[1];
    const float* Wk = (const float*)d_in[2];
    const float* Wv = (const float*)d_in[3];
    float* out = (float*)d_out;

    cudaFuncSetAttribute(k_qkv,    cudaFuncAttributeMaxDynamicSharedMemorySize, SMEM_G);
    cudaFuncSetAttribute(k_scores, cudaFuncAttributeMaxDynamicSharedMemorySize, SMEM_G);
    cudaFuncSetAttribute(k_pv,     cudaFuncAttributeMaxDynamicSharedMemorySize, SMEM_G);

    fp16* xh;
    cudaGetSymbolAddress((void**)&xh, g_Xh);

    k_cvtX<<<MS * Dd / 4 / 256, 256>>>(X, xh);                       // idx 0
    k_cvtW<<<dim3(Dd * Dd / 4 / 256, 3), 256>>>(Wq, Wk, Wv);         // idx 1
    k_qkv<<<dim3(Dd / 128, MS / 128, 3), NT, SMEM_G>>>();            // idx 2
    k_scores<<<dim3(528, Bz), NT, SMEM_G>>>();                       // idx 3 (ncu)
    k_pv<<<dim3(Dd / 128, Sq / 128, Bz), NT, SMEM_G>>>(out);         // idx 4
}